// round 16
// baseline (speedup 1.0000x reference)
#include <cuda_runtime.h>
#include <cuda_fp16.h>
#include <cstdint>

// Problem constants
constexpr int BATCH = 4;
constexpr int SEQ   = 2048;
constexpr int DIM   = 128;
constexpr int HD    = 16;
constexpr int ROWS  = BATCH * SEQ;        // 8192
constexpr int NPAIR = BATCH * 7;          // head 7 is dead
constexpr int QH    = BATCH * 8 * SEQ;    // partial-array stride
constexpr int KSPLIT = 4;
constexpr int BK    = 64;
constexpr int QTILE = 64;
constexpr int NB    = (SEQ / KSPLIT) / BK;   // 8 key-blocks per CTA

// Scratch (device globals — no allocation allowed)
__device__ uint32_t g_xh[ROWS * 64];          // x as packed f16 pairs
__device__ uint32_t g_wh[3][DIM * 64];        // Wq/Wk/Wv f16 pairs (Wk pre-scaled)
__device__ uint32_t g_qh[ROWS * 64];
__device__ uint32_t g_kh[ROWS * 64];
__device__ uint32_t g_vh[ROWS * 64];
__device__ float g_lwT[DIM * DIM];
__device__ float g_maskf[ROWS];
__device__ float g_po[(size_t)KSPLIT * QH * HD];
__device__ float2 g_pml[(size_t)KSPLIT * QH];   // (m, l) packed
__device__ float g_xo[(size_t)ROWS * DIM];      // merged attn out, head-reordered f32

__constant__ int c_head_order[8] = {0, 1, 1, 2, 3, 4, 5, 6};

// ---------------------------------------------------------------------------
// Helpers
// ---------------------------------------------------------------------------
typedef unsigned long long u64;

__device__ __forceinline__ u64 pk2(float lo, float hi) {
    u64 r; asm("mov.b64 %0,{%1,%2};" : "=l"(r) : "f"(lo), "f"(hi)); return r;
}
__device__ __forceinline__ u64 fma2_(u64 a, u64 b, u64 c) {
    u64 d; asm("fma.rn.f32x2 %0,%1,%2,%3;" : "=l"(d) : "l"(a), "l"(b), "l"(c)); return d;
}
__device__ __forceinline__ float ex2f(float x) {
    float y; asm("ex2.approx.ftz.f32 %0,%1;" : "=f"(y) : "f"(x)); return y;
}
__device__ __forceinline__ uint32_t ex2h2(uint32_t x) {
    uint32_t y; asm("ex2.approx.f16x2 %0,%1;" : "=r"(y) : "r"(x)); return y;
}
__device__ __forceinline__ uint32_t h2pack(float lo, float hi) {
    uint32_t r;
    asm("cvt.rn.f16x2.f32 %0, %1, %2;" : "=r"(r) : "f"(hi), "f"(lo));
    return r;
}
__device__ __forceinline__ uint32_t smem_u32(const void* p) {
    uint32_t a;
    asm("{ .reg .u64 t; cvta.to.shared.u64 t, %1; cvt.u32.u64 %0, t; }"
        : "=r"(a) : "l"(p));
    return a;
}
__device__ __forceinline__ void ldsm4(uint32_t* r, uint32_t addr) {
    asm volatile("ldmatrix.sync.aligned.m8n8.x4.shared.b16 {%0,%1,%2,%3}, [%4];"
                 : "=r"(r[0]), "=r"(r[1]), "=r"(r[2]), "=r"(r[3]) : "r"(addr));
}
__device__ __forceinline__ void ldsm4t(uint32_t* r, uint32_t addr) {
    asm volatile("ldmatrix.sync.aligned.m8n8.x4.trans.shared.b16 {%0,%1,%2,%3}, [%4];"
                 : "=r"(r[0]), "=r"(r[1]), "=r"(r[2]), "=r"(r[3]) : "r"(addr));
}
__device__ __forceinline__ void mma_f16(float* d, const uint32_t* a,
                                        uint32_t b0, uint32_t b1) {
    asm volatile(
        "mma.sync.aligned.m16n8k16.row.col.f32.f16.f16.f32 "
        "{%0,%1,%2,%3},{%4,%5,%6,%7},{%8,%9},{%0,%1,%2,%3};"
        : "+f"(d[0]), "+f"(d[1]), "+f"(d[2]), "+f"(d[3])
        : "r"(a[0]), "r"(a[1]), "r"(a[2]), "r"(a[3]), "r"(b0), "r"(b1));
}
__device__ __forceinline__ void cp16(uint32_t dst, const void* src) {
    asm volatile("cp.async.ca.shared.global [%0], [%1], 16;"
                 :: "r"(dst), "l"(src) : "memory");
}
__device__ __forceinline__ void cp_commit() {
    asm volatile("cp.async.commit_group;" ::: "memory");
}
template <int N> __device__ __forceinline__ void cp_wait() {
    asm volatile("cp.async.wait_group %0;" :: "n"(N) : "memory");
}

constexpr uint32_t ONES_H2 = 0x3C003C00u;  // (1.0h, 1.0h)

// ---------------------------------------------------------------------------
// Kernel A: fused prep — x->f16, W->f16 (Wk pre-scaled), lin_w transpose, mask.
// ---------------------------------------------------------------------------
__global__ __launch_bounds__(256) void prep_kernel(
    const float* __restrict__ x,
    const float* __restrict__ wq, const float* __restrict__ wk,
    const float* __restrict__ wv, const float* __restrict__ lin_w,
    const int*   __restrict__ mraw)
{
    const int gid = blockIdx.x * 256 + threadIdx.x;
    const int nth = gridDim.x * 256;

    for (int i = gid; i < ROWS * 64; i += nth) {
        float2 v = *(const float2*)&x[(size_t)i * 2];
        g_xh[i] = h2pack(v.x, v.y);
    }
    const float sc = 0.08838834764831845f * 1.4426950408889634f;
    for (int idx = gid; idx < 3 * DIM * 64; idx += nth) {
        int s = idx / (DIM * 64);
        int r = idx - s * (DIM * 64);
        const float* W = (s == 0) ? wq : (s == 1) ? wk : wv;
        float2 w2 = *(const float2*)&W[(size_t)r * 2];
        float f = (s == 1) ? sc : 1.0f;
        g_wh[s][r] = h2pack(w2.x * f, w2.y * f);
    }
    for (int idx = gid; idx < DIM * DIM; idx += nth) {
        int j = idx >> 7, c = idx & 127;
        g_lwT[c * 128 + j] = lin_w[idx];
    }
    __shared__ int is64;
    if (threadIdx.x == 0) {
        int acc = 0;
        for (int i = 0; i < 64; i++) acc |= mraw[2 * i + 1];
        is64 = (acc == 0);
    }
    __syncthreads();
    for (int idx = gid; idx < ROWS; idx += nth) {
        int v = is64 ? mraw[2 * idx] : mraw[idx];
        g_maskf[idx] = (v == 0) ? -1442.6950408889634f : 0.0f;
    }
}

// ---------------------------------------------------------------------------
// Kernel 1: QKV projection on tensor cores; 64-row tiles (W staging amortized).
// 8 warps = 4 row-groups (16 rows) x 2 col-groups (64 cols).
// ---------------------------------------------------------------------------
__global__ __launch_bounds__(256) void qkv_kernel()
{
    __shared__ uint32_t xs[64 * 68];    // 17.4 KB
    __shared__ uint32_t ws[128 * 68];   // 34.8 KB

    const int tid  = threadIdx.x;
    const int row0 = blockIdx.x * 64;
    const int s    = blockIdx.y;
    uint32_t* out  = (s == 0) ? g_qh : (s == 1) ? g_kh : g_vh;
    const uint32_t* wsrc = g_wh[s];

    // stage x tile (4096 words) and W (8192 words)
#pragma unroll
    for (int it = 0; it < 4; it++) {
        int j = tid + it * 256;
        int w4 = j * 4, r = w4 >> 6, c = w4 & 63;
        *(uint4*)&xs[r * 68 + c] = *(const uint4*)&g_xh[(size_t)(row0 + r) * 64 + c];
    }
#pragma unroll
    for (int it = 0; it < 8; it++) {
        int j = tid + it * 256;
        int w4 = j * 4, d = w4 >> 6, c = w4 & 63;
        *(uint4*)&ws[d * 68 + c] = *(const uint4*)&wsrc[d * 64 + c];
    }
    __syncthreads();

    const int w    = tid >> 5;
    const int lane = tid & 31;
    const int g    = lane >> 2;
    const int q4   = lane & 3;
    const int rowg = (w & 3) * 16;      // 4 row groups
    const int colg = (w >> 2) * 64;     // 2 col groups

    const uint32_t xs_base = smem_u32(xs);
    const uint32_t ws_base = smem_u32(ws);
    const uint32_t aaddr = xs_base + (uint32_t)((rowg + (lane & 15)) * 68 + ((lane >= 16) ? 4 : 0)) * 4;
    const uint32_t baddr = ws_base + (uint32_t)((lane & 15) * 68 + ((lane >= 16) ? 4 : 0)) * 4;

    float c[8][4];
#pragma unroll
    for (int t = 0; t < 8; t++)
#pragma unroll
        for (int i = 0; i < 4; i++) c[t][i] = 0.f;

#pragma unroll
    for (int kc = 0; kc < 8; kc++) {
        uint32_t a[4];
        ldsm4(a, aaddr + kc * 32);
#pragma unroll
        for (int np = 0; np < 4; np++) {
            const int n0 = colg + np * 16;
            if (n0 >= 112) continue;     // head 7 dead
            uint32_t bb[4];
            ldsm4t(bb, baddr + (uint32_t)kc * 16 * 272 + (uint32_t)(n0 >> 1) * 4);
            mma_f16(c[np * 2],     a, bb[0], bb[1]);
            mma_f16(c[np * 2 + 1], a, bb[2], bb[3]);
        }
    }

    const int row = row0 + rowg + g;
#pragma unroll
    for (int np = 0; np < 4; np++) {
#pragma unroll
        for (int nt = 0; nt < 2; nt++) {
            const int n0t = colg + np * 16 + nt * 8;
            if (n0t >= 112) continue;
            const int cp = (n0t >> 1) + q4;
            const int t = np * 2 + nt;
            out[(size_t)row * 64 + cp]       = h2pack(c[t][0], c[t][1]);
            out[(size_t)(row + 8) * 64 + cp] = h2pack(c[t][2], c[t][3]);
        }
    }
}

// ---------------------------------------------------------------------------
// Kernel 3: flash attention; 2-buffer cp.async pipeline (R12 proven config).
// ---------------------------------------------------------------------------
__global__ __launch_bounds__(128, 8) void attn_kernel()
{
    __shared__ __align__(16) __half Ksm[2][BK][40];
    __shared__ __align__(16) __half Vsm[2][BK][40];
    __shared__ __align__(16) float  ms[2][BK];

    const int tid  = threadIdx.x;
    const int lane = tid & 31;
    const int g    = lane >> 2;
    const int q4   = lane & 3;
    const int pair = blockIdx.y;
    const int b    = pair / 7;
    const int h    = pair - b * 7;
    const int q0   = blockIdx.x * QTILE + (tid >> 5) * 16;
    const int kstart = blockIdx.z * (SEQ / KSPLIT);

    const int row_lo = q0 + g;
    const int row_hi = row_lo + 8;

    uint32_t aQ[4];
    aQ[0] = g_qh[(size_t)(b * SEQ + row_lo) * 64 + h * 8 + q4];
    aQ[1] = g_qh[(size_t)(b * SEQ + row_hi) * 64 + h * 8 + q4];
    aQ[2] = g_qh[(size_t)(b * SEQ + row_lo) * 64 + h * 8 + q4 + 4];
    aQ[3] = g_qh[(size_t)(b * SEQ + row_hi) * 64 + h * 8 + q4 + 4];

    float m_lo = -1e30f, m_hi = -1e30f;
    float o[2][4], lacc[4];
#pragma unroll
    for (int nt = 0; nt < 2; nt++)
#pragma unroll
        for (int i = 0; i < 4; i++) o[nt][i] = 0.f;
#pragma unroll
    for (int i = 0; i < 4; i++) lacc[i] = 0.f;

    const uint32_t ksm0 = smem_u32(Ksm);
    const uint32_t vsm0 = smem_u32(Vsm);
    const uint32_t msm0 = smem_u32(ms);
    const uint32_t laneK = (uint32_t)(((lane & 7) + ((lane & 16) ? 8 : 0)) * 80
                                      + ((lane & 8) ? 16 : 0));
    const uint32_t laneV = (uint32_t)((lane & 15) * 80 + ((lane & 16) ? 16 : 0));

    const int skey = tid >> 1;
    const int koff = (tid & 1) * 4;
    const uint32_t sdst = (uint32_t)(skey * 80 + koff * 4);

    auto stage = [&](int buf, int kb) {
        size_t base = (size_t)(b * SEQ + kb + skey) * 64 + h * 8 + koff;
        cp16(ksm0 + (uint32_t)buf * 5120u + sdst, &g_kh[base]);
        cp16(vsm0 + (uint32_t)buf * 5120u + sdst, &g_vh[base]);
        if (tid < 16)
            cp16(msm0 + (uint32_t)buf * 256u + (uint32_t)tid * 16u,
                 &g_maskf[b * SEQ + kb + tid * 4]);
        cp_commit();
    };

    stage(0, kstart);
    stage(1, kstart + BK);

    for (int i = 0; i < NB; i++) {
        if (i < NB - 1) cp_wait<1>(); else cp_wait<0>();
        __syncthreads();
        const int buf = i & 1;
        const uint32_t kaddr = ksm0 + (uint32_t)buf * 5120u + laneK;
        const uint32_t vaddr = vsm0 + (uint32_t)buf * 5120u + laneV;
        const float* msp = ms[buf];

        // ---- QK^T: 8 tiles via 4 ldmatrix.x4; mask initializes accumulators ----
        float s[8][4];
#pragma unroll
        for (int tp = 0; tp < 4; tp++) {
            uint32_t kf[4];
            ldsm4(kf, kaddr + (uint32_t)tp * 1280);
            float2 mk0 = *(const float2*)&msp[(2 * tp) * 8 + 2 * q4];
            float2 mk1 = *(const float2*)&msp[(2 * tp + 1) * 8 + 2 * q4];
            s[2 * tp][0] = mk0.x; s[2 * tp][1] = mk0.y;
            s[2 * tp][2] = mk0.x; s[2 * tp][3] = mk0.y;
            s[2 * tp + 1][0] = mk1.x; s[2 * tp + 1][1] = mk1.y;
            s[2 * tp + 1][2] = mk1.x; s[2 * tp + 1][3] = mk1.y;
            mma_f16(s[2 * tp],     aQ, kf[0], kf[1]);
            mma_f16(s[2 * tp + 1], aQ, kf[2], kf[3]);
        }

        // ---- block row max ----
        float bm_lo = -1e30f, bm_hi = -1e30f;
#pragma unroll
        for (int t = 0; t < 8; t++) {
            bm_lo = fmaxf(bm_lo, fmaxf(s[t][0], s[t][1]));
            bm_hi = fmaxf(bm_hi, fmaxf(s[t][2], s[t][3]));
        }
        bm_lo = fmaxf(bm_lo, __shfl_xor_sync(0xffffffffu, bm_lo, 1));
        bm_lo = fmaxf(bm_lo, __shfl_xor_sync(0xffffffffu, bm_lo, 2));
        bm_hi = fmaxf(bm_hi, __shfl_xor_sync(0xffffffffu, bm_hi, 1));
        bm_hi = fmaxf(bm_hi, __shfl_xor_sync(0xffffffffu, bm_hi, 2));

        if ((bm_lo > m_lo) | (bm_hi > m_hi)) {
            float mn_lo = fmaxf(m_lo, bm_lo);
            float mn_hi = fmaxf(m_hi, bm_hi);
            float c_lo = ex2f(m_lo - mn_lo);
            float c_hi = ex2f(m_hi - mn_hi);
            lacc[0] *= c_lo; lacc[2] *= c_hi;
#pragma unroll
            for (int nt = 0; nt < 2; nt++) {
                o[nt][0] *= c_lo; o[nt][1] *= c_lo;
                o[nt][2] *= c_hi; o[nt][3] *= c_hi;
            }
            m_lo = mn_lo; m_hi = mn_hi;
        }

        // ---- exp (f16x2) + PV + l per 16-key group ----
#pragma unroll
        for (int G = 0; G < 4; G++) {
            uint32_t aF[4];
#pragma unroll
            for (int u = 0; u < 2; u++) {
                const int t = 2 * G + u;
                float d0 = s[t][0] - m_lo, d1 = s[t][1] - m_lo;
                float d2 = s[t][2] - m_hi, d3 = s[t][3] - m_hi;
                aF[u * 2 + 0] = ex2h2(h2pack(d0, d1));
                aF[u * 2 + 1] = ex2h2(h2pack(d2, d3));
            }
            uint32_t vf[4];
            ldsm4t(vf, vaddr + (uint32_t)G * 1280);
            mma_f16(o[0], aF, vf[0], vf[1]);
            mma_f16(o[1], aF, vf[2], vf[3]);
            mma_f16(lacc, aF, ONES_H2, ONES_H2);
        }

        __syncthreads();
        if (i + 2 < NB) stage(buf, kstart + (i + 2) * BK);
    }

    // ---- finalize ----
    const int z = blockIdx.z;
    const size_t qlo = (size_t)pair * SEQ + row_lo;
    const size_t qhi = (size_t)pair * SEQ + row_hi;
    float* plo = g_po + ((size_t)z * QH + qlo) * HD;
    float* phi = g_po + ((size_t)z * QH + qhi) * HD;
    *(float2*)&plo[2 * q4]     = make_float2(o[0][0], o[0][1]);
    *(float2*)&plo[8 + 2 * q4] = make_float2(o[1][0], o[1][1]);
    *(float2*)&phi[2 * q4]     = make_float2(o[0][2], o[0][3]);
    *(float2*)&phi[8 + 2 * q4] = make_float2(o[1][2], o[1][3]);
    if (q4 == 0) {
        g_pml[(size_t)z * QH + qlo] = make_float2(m_lo, lacc[0]);
        g_pml[(size_t)z * QH + qhi] = make_float2(m_hi, lacc[2]);
    }
}

// ---------------------------------------------------------------------------
// Kernel 3b: standalone merge — thread = (row, slot, quarter); 262144 threads.
// ---------------------------------------------------------------------------
__global__ __launch_bounds__(256) void merge_kernel()
{
    const int gid  = blockIdx.x * 256 + threadIdx.x;   // 0..ROWS*32-1
    const int row  = gid >> 5;
    const int sub  = gid & 31;
    const int slot = sub >> 2;
    const int quar = sub & 3;
    const int b    = row >> 11;
    const int rin  = row & 2047;
    const int hh   = c_head_order[slot];
    const size_t qidx = (size_t)(b * 7 + hh) * SEQ + rin;

    float m[KSPLIT], l[KSPLIT], c[KSPLIT];
    float mm = -1e30f;
#pragma unroll
    for (int z = 0; z < KSPLIT; z++) {
        float2 ml = g_pml[(size_t)z * QH + qidx];
        m[z] = ml.x; l[z] = ml.y;
        mm = fmaxf(mm, m[z]);
    }
    float denom = 0.f;
#pragma unroll
    for (int z = 0; z < KSPLIT; z++) {
        c[z] = ex2f(m[z] - mm);
        denom += l[z] * c[z];
    }
    float inv = 1.0f / denom;
#pragma unroll
    for (int z = 0; z < KSPLIT; z++) c[z] *= inv;

    float4 acc = make_float4(0.f, 0.f, 0.f, 0.f);
#pragma unroll
    for (int z = 0; z < KSPLIT; z++) {
        float4 a = *(const float4*)(g_po + ((size_t)z * QH + qidx) * HD + quar * 4);
        acc.x = fmaf(a.x, c[z], acc.x);
        acc.y = fmaf(a.y, c[z], acc.y);
        acc.z = fmaf(a.z, c[z], acc.z);
        acc.w = fmaf(a.w, c[z], acc.w);
    }
    *(float4*)&g_xo[(size_t)row * DIM + slot * 16 + quar * 4] = acc;
}

// ---------------------------------------------------------------------------
// Kernel 4: output projection — 8-row tiles (grid 1024) for latency cover.
// ---------------------------------------------------------------------------
__global__ __launch_bounds__(256) void proj_kernel(
    const float* __restrict__ lin_b,
    float* __restrict__ y)
{
    __shared__ u64 xd[8][128];
    const int tid  = threadIdx.x;
    const int row0 = blockIdx.x * 8;

    // coalesced tile load: 8x128 f32 = 256 float4; dup-pack into smem
    {
        const float4* src = (const float4*)&g_xo[(size_t)row0 * DIM];
        float4 v = src[tid];
        int r = tid >> 5, cc = (tid & 31) * 4;
        xd[r][cc + 0] = pk2(v.x, v.x);
        xd[r][cc + 1] = pk2(v.y, v.y);
        xd[r][cc + 2] = pk2(v.z, v.z);
        xd[r][cc + 3] = pk2(v.w, v.w);
    }
    __syncthreads();

    const int jh = tid & 63;
    const int rg = tid >> 6;            // 0..3; rows rg, rg+4

    float2 b2 = *(const float2*)&lin_b[jh * 2];
    const u64 bias = pk2(b2.x, b2.y);
    u64 acc0 = bias, acc1 = bias;

    const u64* Wp = (const u64*)g_lwT;
#pragma unroll
    for (int d0 = 0; d0 < 128; d0 += 8) {
        u64 w[8];
#pragma unroll
        for (int i = 0; i < 8; i++) w[i] = Wp[(d0 + i) * 64 + jh];
#pragma unroll
        for (int i = 0; i < 8; i++) {
            acc0 = fma2_(xd[rg][d0 + i],     w[i], acc0);
            acc1 = fma2_(xd[rg + 4][d0 + i], w[i], acc1);
        }
    }
    u64* yp = (u64*)y;
    yp[(size_t)(row0 + rg) * 64 + jh]     = acc0;
    yp[(size_t)(row0 + rg + 4) * 64 + jh] = acc1;
}

// ---------------------------------------------------------------------------
extern "C" void kernel_launch(void* const* d_in, const int* in_sizes, int n_in,
                              void* d_out, int out_size)
{
    const float* x    = (const float*)d_in[0];
    const int*   mraw = (const int*)  d_in[1];
    const float* wq   = (const float*)d_in[2];
    const float* wk   = (const float*)d_in[3];
    const float* wv   = (const float*)d_in[4];
    const float* lw   = (const float*)d_in[5];
    const float* lb   = (const float*)d_in[6];
    float*       y    = (float*)d_out;

    prep_kernel<<<256, 256>>>(x, wq, wk, wv, lw, mraw);
    qkv_kernel<<<dim3(ROWS / 64, 3), 256>>>();
    attn_kernel<<<dim3(SEQ / QTILE, NPAIR, KSPLIT), 128>>>();
    merge_kernel<<<ROWS * 32 / 256, 256>>>();
    proj_kernel<<<ROWS / 8, 256>>>(lb, y);
}

// round 17
// speedup vs baseline: 1.1302x; 1.1302x over previous
#include <cuda_runtime.h>
#include <cuda_fp16.h>
#include <cstdint>

// Problem constants
constexpr int BATCH = 4;
constexpr int SEQ   = 2048;
constexpr int DIM   = 128;
constexpr int HD    = 16;
constexpr int ROWS  = BATCH * SEQ;        // 8192
constexpr int NPAIR = BATCH * 7;          // head 7 is dead
constexpr int QH    = BATCH * 8 * SEQ;    // partial-array stride
constexpr int KSPLIT = 4;
constexpr int BK    = 64;
constexpr int QTILE = 128;                // 8 warps x 16 query rows
constexpr int NB    = (SEQ / KSPLIT) / BK;   // 8 key-blocks per CTA

// Scratch (device globals — no allocation allowed)
__device__ uint32_t g_xh[ROWS * 64];          // x as packed f16 pairs
__device__ uint32_t g_wh[3][DIM * 64];        // Wq/Wk/Wv f16 pairs (Wk pre-scaled)
__device__ uint32_t g_qh[ROWS * 64];
__device__ uint32_t g_kh[ROWS * 64];
__device__ uint32_t g_vh[ROWS * 64];
__device__ float g_lwT[DIM * DIM];
__device__ float g_maskf[ROWS];
__device__ float g_po[(size_t)KSPLIT * QH * HD];
__device__ float g_pm[(size_t)KSPLIT * QH];
__device__ float g_pl[(size_t)KSPLIT * QH];

__constant__ int c_head_order[8] = {0, 1, 1, 2, 3, 4, 5, 6};

// ---------------------------------------------------------------------------
// Helpers
// ---------------------------------------------------------------------------
typedef unsigned long long u64;

__device__ __forceinline__ u64 pk2(float lo, float hi) {
    u64 r; asm("mov.b64 %0,{%1,%2};" : "=l"(r) : "f"(lo), "f"(hi)); return r;
}
__device__ __forceinline__ u64 fma2_(u64 a, u64 b, u64 c) {
    u64 d; asm("fma.rn.f32x2 %0,%1,%2,%3;" : "=l"(d) : "l"(a), "l"(b), "l"(c)); return d;
}
__device__ __forceinline__ float ex2f(float x) {
    float y; asm("ex2.approx.ftz.f32 %0,%1;" : "=f"(y) : "f"(x)); return y;
}
__device__ __forceinline__ uint32_t ex2h2(uint32_t x) {
    uint32_t y; asm("ex2.approx.f16x2 %0,%1;" : "=r"(y) : "r"(x)); return y;
}
__device__ __forceinline__ uint32_t h2pack(float lo, float hi) {
    uint32_t r;
    asm("cvt.rn.f16x2.f32 %0, %1, %2;" : "=r"(r) : "f"(hi), "f"(lo));
    return r;
}
__device__ __forceinline__ uint32_t smem_u32(const void* p) {
    uint32_t a;
    asm("{ .reg .u64 t; cvta.to.shared.u64 t, %1; cvt.u32.u64 %0, t; }"
        : "=r"(a) : "l"(p));
    return a;
}
__device__ __forceinline__ void ldsm4(uint32_t* r, uint32_t addr) {
    asm volatile("ldmatrix.sync.aligned.m8n8.x4.shared.b16 {%0,%1,%2,%3}, [%4];"
                 : "=r"(r[0]), "=r"(r[1]), "=r"(r[2]), "=r"(r[3]) : "r"(addr));
}
__device__ __forceinline__ void ldsm4t(uint32_t* r, uint32_t addr) {
    asm volatile("ldmatrix.sync.aligned.m8n8.x4.trans.shared.b16 {%0,%1,%2,%3}, [%4];"
                 : "=r"(r[0]), "=r"(r[1]), "=r"(r[2]), "=r"(r[3]) : "r"(addr));
}
__device__ __forceinline__ void mma_f16(float* d, const uint32_t* a,
                                        uint32_t b0, uint32_t b1) {
    asm volatile(
        "mma.sync.aligned.m16n8k16.row.col.f32.f16.f16.f32 "
        "{%0,%1,%2,%3},{%4,%5,%6,%7},{%8,%9},{%0,%1,%2,%3};"
        : "+f"(d[0]), "+f"(d[1]), "+f"(d[2]), "+f"(d[3])
        : "r"(a[0]), "r"(a[1]), "r"(a[2]), "r"(a[3]), "r"(b0), "r"(b1));
}
__device__ __forceinline__ void cp16(uint32_t dst, const void* src) {
    asm volatile("cp.async.ca.shared.global [%0], [%1], 16;"
                 :: "r"(dst), "l"(src) : "memory");
}
__device__ __forceinline__ void cp_commit() {
    asm volatile("cp.async.commit_group;" ::: "memory");
}
template <int N> __device__ __forceinline__ void cp_wait() {
    asm volatile("cp.async.wait_group %0;" :: "n"(N) : "memory");
}

constexpr uint32_t ONES_H2 = 0x3C003C00u;  // (1.0h, 1.0h)

// ---------------------------------------------------------------------------
// Kernel A: fused prep — x->f16, W->f16 (Wk pre-scaled), lin_w transpose, mask.
// ---------------------------------------------------------------------------
__global__ __launch_bounds__(256) void prep_kernel(
    const float* __restrict__ x,
    const float* __restrict__ wq, const float* __restrict__ wk,
    const float* __restrict__ wv, const float* __restrict__ lin_w,
    const int*   __restrict__ mraw)
{
    const int gid = blockIdx.x * 256 + threadIdx.x;
    const int nth = gridDim.x * 256;

    for (int i = gid; i < ROWS * 64; i += nth) {
        float2 v = *(const float2*)&x[(size_t)i * 2];
        g_xh[i] = h2pack(v.x, v.y);
    }
    const float sc = 0.08838834764831845f * 1.4426950408889634f;
    for (int idx = gid; idx < 3 * DIM * 64; idx += nth) {
        int s = idx / (DIM * 64);
        int r = idx - s * (DIM * 64);
        const float* W = (s == 0) ? wq : (s == 1) ? wk : wv;
        float2 w2 = *(const float2*)&W[(size_t)r * 2];
        float f = (s == 1) ? sc : 1.0f;
        g_wh[s][r] = h2pack(w2.x * f, w2.y * f);
    }
    for (int idx = gid; idx < DIM * DIM; idx += nth) {
        int j = idx >> 7, c = idx & 127;
        g_lwT[c * 128 + j] = lin_w[idx];
    }
    __shared__ int is64;
    if (threadIdx.x == 0) {
        int acc = 0;
        for (int i = 0; i < 64; i++) acc |= mraw[2 * i + 1];
        is64 = (acc == 0);
    }
    __syncthreads();
    for (int idx = gid; idx < ROWS; idx += nth) {
        int v = is64 ? mraw[2 * idx] : mraw[idx];
        g_maskf[idx] = (v == 0) ? -1442.6950408889634f : 0.0f;
    }
}

// ---------------------------------------------------------------------------
// Kernel 1: QKV projection on tensor cores (f16 mma, ldmatrix). 32-row tiles.
// ---------------------------------------------------------------------------
__global__ __launch_bounds__(256) void qkv_kernel()
{
    __shared__ uint32_t xs[32 * 68];
    __shared__ uint32_t ws[128 * 68];

    const int tid  = threadIdx.x;
    const int row0 = blockIdx.x * 32;
    const int s    = blockIdx.y;
    uint32_t* out  = (s == 0) ? g_qh : (s == 1) ? g_kh : g_vh;
    const uint32_t* wsrc = g_wh[s];

#pragma unroll
    for (int it = 0; it < 2; it++) {
        int j = tid + it * 256;
        int w4 = j * 4, r = w4 >> 6, c = w4 & 63;
        *(uint4*)&xs[r * 68 + c] = *(const uint4*)&g_xh[(size_t)(row0 + r) * 64 + c];
    }
#pragma unroll
    for (int it = 0; it < 8; it++) {
        int j = tid + it * 256;
        int w4 = j * 4, d = w4 >> 6, c = w4 & 63;
        *(uint4*)&ws[d * 68 + c] = *(const uint4*)&wsrc[d * 64 + c];
    }
    __syncthreads();

    const int w    = tid >> 5;
    const int lane = tid & 31;
    const int g    = lane >> 2;
    const int q4   = lane & 3;
    const int rowg = (w & 1) * 16;
    const int colg = (w >> 1) * 32;

    const uint32_t xs_base = smem_u32(xs);
    const uint32_t ws_base = smem_u32(ws);
    const uint32_t aaddr = xs_base + (uint32_t)((rowg + (lane & 15)) * 68 + ((lane >= 16) ? 4 : 0)) * 4;
    const uint32_t baddr = ws_base + (uint32_t)((lane & 15) * 68 + ((lane >= 16) ? 4 : 0)) * 4;

    float c[4][4];
#pragma unroll
    for (int t = 0; t < 4; t++)
#pragma unroll
        for (int i = 0; i < 4; i++) c[t][i] = 0.f;

#pragma unroll
    for (int kc = 0; kc < 8; kc++) {
        uint32_t a[4];
        ldsm4(a, aaddr + kc * 32);
#pragma unroll
        for (int np = 0; np < 2; np++) {
            const int n0 = colg + np * 16;
            if (n0 >= 112) continue;
            uint32_t bb[4];
            ldsm4t(bb, baddr + (uint32_t)kc * 16 * 272 + (uint32_t)(n0 >> 1) * 4);
            mma_f16(c[np * 2],     a, bb[0], bb[1]);
            mma_f16(c[np * 2 + 1], a, bb[2], bb[3]);
        }
    }

    const int row = row0 + rowg + g;
#pragma unroll
    for (int np = 0; np < 2; np++) {
#pragma unroll
        for (int nt = 0; nt < 2; nt++) {
            const int n0t = colg + np * 16 + nt * 8;
            if (n0t >= 112) continue;
            const int cp = (n0t >> 1) + q4;
            const int t = np * 2 + nt;
            out[(size_t)row * 64 + cp]       = h2pack(c[t][0], c[t][1]);
            out[(size_t)(row + 8) * 64 + cp] = h2pack(c[t][2], c[t][3]);
        }
    }
}

// ---------------------------------------------------------------------------
// Kernel 3: flash attention; QTILE=128 (256 threads, 8 warps x 16 rows).
// K/V tiles shared across 2x queries vs R12; staging split K/V by thread half.
// 2-buffer cp.async pipeline; math identical to R12.
// ---------------------------------------------------------------------------
__global__ __launch_bounds__(256, 4) void attn_kernel()
{
    __shared__ __align__(16) __half Ksm[2][BK][40];
    __shared__ __align__(16) __half Vsm[2][BK][40];
    __shared__ __align__(16) float  ms[2][BK];

    const int tid  = threadIdx.x;
    const int lane = tid & 31;
    const int g    = lane >> 2;
    const int q4   = lane & 3;
    const int pair = blockIdx.y;
    const int b    = pair / 7;
    const int h    = pair - b * 7;
    const int q0   = blockIdx.x * QTILE + (tid >> 5) * 16;
    const int kstart = blockIdx.z * (SEQ / KSPLIT);

    const int row_lo = q0 + g;
    const int row_hi = row_lo + 8;

    uint32_t aQ[4];
    aQ[0] = g_qh[(size_t)(b * SEQ + row_lo) * 64 + h * 8 + q4];
    aQ[1] = g_qh[(size_t)(b * SEQ + row_hi) * 64 + h * 8 + q4];
    aQ[2] = g_qh[(size_t)(b * SEQ + row_lo) * 64 + h * 8 + q4 + 4];
    aQ[3] = g_qh[(size_t)(b * SEQ + row_hi) * 64 + h * 8 + q4 + 4];

    float m_lo = -1e30f, m_hi = -1e30f;
    float o[2][4], lacc[4];
#pragma unroll
    for (int nt = 0; nt < 2; nt++)
#pragma unroll
        for (int i = 0; i < 4; i++) o[nt][i] = 0.f;
#pragma unroll
    for (int i = 0; i < 4; i++) lacc[i] = 0.f;

    const uint32_t ksm0 = smem_u32(Ksm);
    const uint32_t vsm0 = smem_u32(Vsm);
    const uint32_t msm0 = smem_u32(ms);
    const uint32_t laneK = (uint32_t)(((lane & 7) + ((lane & 16) ? 8 : 0)) * 80
                                      + ((lane & 8) ? 16 : 0));
    const uint32_t laneV = (uint32_t)((lane & 15) * 80 + ((lane & 16) ? 16 : 0));

    // staging: threads 0-127 stage K, threads 128-255 stage V (1 cp16 each)
    const int  sel  = tid >> 7;
    const int  t2   = tid & 127;
    const int  skey = t2 >> 1;
    const int  koff = (t2 & 1) * 4;
    const uint32_t sdst = (uint32_t)(skey * 80 + koff * 4);
    const uint32_t* gsrc = sel ? g_vh : g_kh;
    const uint32_t  smbase = sel ? vsm0 : ksm0;

    auto stage = [&](int buf, int kb) {
        size_t base = (size_t)(b * SEQ + kb + skey) * 64 + h * 8 + koff;
        cp16(smbase + (uint32_t)buf * 5120u + sdst, &gsrc[base]);
        if (tid < 16)
            cp16(msm0 + (uint32_t)buf * 256u + (uint32_t)tid * 16u,
                 &g_maskf[b * SEQ + kb + tid * 4]);
        cp_commit();
    };

    stage(0, kstart);
    stage(1, kstart + BK);

    for (int i = 0; i < NB; i++) {
        if (i < NB - 1) cp_wait<1>(); else cp_wait<0>();
        __syncthreads();
        const int buf = i & 1;
        const uint32_t kaddr = ksm0 + (uint32_t)buf * 5120u + laneK;
        const uint32_t vaddr = vsm0 + (uint32_t)buf * 5120u + laneV;
        const float* msp = ms[buf];

        // ---- QK^T: 8 tiles via 4 ldmatrix.x4; mask initializes accumulators ----
        float s[8][4];
#pragma unroll
        for (int tp = 0; tp < 4; tp++) {
            uint32_t kf[4];
            ldsm4(kf, kaddr + (uint32_t)tp * 1280);
            float2 mk0 = *(const float2*)&msp[(2 * tp) * 8 + 2 * q4];
            float2 mk1 = *(const float2*)&msp[(2 * tp + 1) * 8 + 2 * q4];
            s[2 * tp][0] = mk0.x; s[2 * tp][1] = mk0.y;
            s[2 * tp][2] = mk0.x; s[2 * tp][3] = mk0.y;
            s[2 * tp + 1][0] = mk1.x; s[2 * tp + 1][1] = mk1.y;
            s[2 * tp + 1][2] = mk1.x; s[2 * tp + 1][3] = mk1.y;
            mma_f16(s[2 * tp],     aQ, kf[0], kf[1]);
            mma_f16(s[2 * tp + 1], aQ, kf[2], kf[3]);
        }

        // ---- block row max ----
        float bm_lo = -1e30f, bm_hi = -1e30f;
#pragma unroll
        for (int t = 0; t < 8; t++) {
            bm_lo = fmaxf(bm_lo, fmaxf(s[t][0], s[t][1]));
            bm_hi = fmaxf(bm_hi, fmaxf(s[t][2], s[t][3]));
        }
        bm_lo = fmaxf(bm_lo, __shfl_xor_sync(0xffffffffu, bm_lo, 1));
        bm_lo = fmaxf(bm_lo, __shfl_xor_sync(0xffffffffu, bm_lo, 2));
        bm_hi = fmaxf(bm_hi, __shfl_xor_sync(0xffffffffu, bm_hi, 1));
        bm_hi = fmaxf(bm_hi, __shfl_xor_sync(0xffffffffu, bm_hi, 2));

        if ((bm_lo > m_lo) | (bm_hi > m_hi)) {
            float mn_lo = fmaxf(m_lo, bm_lo);
            float mn_hi = fmaxf(m_hi, bm_hi);
            float c_lo = ex2f(m_lo - mn_lo);
            float c_hi = ex2f(m_hi - mn_hi);
            lacc[0] *= c_lo; lacc[2] *= c_hi;
#pragma unroll
            for (int nt = 0; nt < 2; nt++) {
                o[nt][0] *= c_lo; o[nt][1] *= c_lo;
                o[nt][2] *= c_hi; o[nt][3] *= c_hi;
            }
            m_lo = mn_lo; m_hi = mn_hi;
        }

        // ---- exp (f16x2) + PV + l per 16-key group ----
#pragma unroll
        for (int G = 0; G < 4; G++) {
            uint32_t aF[4];
#pragma unroll
            for (int u = 0; u < 2; u++) {
                const int t = 2 * G + u;
                float d0 = s[t][0] - m_lo, d1 = s[t][1] - m_lo;
                float d2 = s[t][2] - m_hi, d3 = s[t][3] - m_hi;
                aF[u * 2 + 0] = ex2h2(h2pack(d0, d1));
                aF[u * 2 + 1] = ex2h2(h2pack(d2, d3));
            }
            uint32_t vf[4];
            ldsm4t(vf, vaddr + (uint32_t)G * 1280);
            mma_f16(o[0], aF, vf[0], vf[1]);
            mma_f16(o[1], aF, vf[2], vf[3]);
            mma_f16(lacc, aF, ONES_H2, ONES_H2);
        }

        __syncthreads();
        if (i + 2 < NB) stage(buf, kstart + (i + 2) * BK);
    }

    // ---- finalize ----
    const int z = blockIdx.z;
    const size_t qlo = (size_t)pair * SEQ + row_lo;
    const size_t qhi = (size_t)pair * SEQ + row_hi;
    float* plo = g_po + ((size_t)z * QH + qlo) * HD;
    float* phi = g_po + ((size_t)z * QH + qhi) * HD;
    *(float2*)&plo[2 * q4]     = make_float2(o[0][0], o[0][1]);
    *(float2*)&plo[8 + 2 * q4] = make_float2(o[1][0], o[1][1]);
    *(float2*)&phi[2 * q4]     = make_float2(o[0][2], o[0][3]);
    *(float2*)&phi[8 + 2 * q4] = make_float2(o[1][2], o[1][3]);
    if (q4 == 0) {
        g_pm[(size_t)z * QH + qlo] = m_lo;
        g_pl[(size_t)z * QH + qlo] = lacc[0];
        g_pm[(size_t)z * QH + qhi] = m_hi;
        g_pl[(size_t)z * QH + qhi] = lacc[2];
    }
}

// ---------------------------------------------------------------------------
// Kernel 4: FUSED merge + gather + output projection (R12-proven).
// 16-row tiles (grid 512); gather thread = (row, slot, half).
// ---------------------------------------------------------------------------
__global__ __launch_bounds__(256) void proj_kernel(
    const float* __restrict__ lin_b,
    float* __restrict__ y)
{
    __shared__ u64 xd[16][128];
    const int tid  = threadIdx.x;
    const int row0 = blockIdx.x * 16;
    const int b    = row0 >> 11;
    const int rin0 = row0 & 2047;

    {
        const int r    = tid >> 4;          // 0..15
        const int slot = (tid >> 1) & 7;    // 0..7
        const int half = tid & 1;           // 0..1
        const int hh   = c_head_order[slot];
        const size_t qidx = (size_t)(b * 7 + hh) * SEQ + rin0 + r;

        float m[KSPLIT], l[KSPLIT], c[KSPLIT];
        float mm = -1e30f;
#pragma unroll
        for (int z = 0; z < KSPLIT; z++) {
            m[z] = g_pm[(size_t)z * QH + qidx];
            l[z] = g_pl[(size_t)z * QH + qidx];
            mm = fmaxf(mm, m[z]);
        }
        float denom = 0.f;
#pragma unroll
        for (int z = 0; z < KSPLIT; z++) {
            c[z] = ex2f(m[z] - mm);
            denom += l[z] * c[z];
        }
        float inv = 1.0f / denom;
#pragma unroll
        for (int z = 0; z < KSPLIT; z++) c[z] *= inv;

        float acc[8];
#pragma unroll
        for (int j = 0; j < 8; j++) acc[j] = 0.f;
#pragma unroll
        for (int z = 0; z < KSPLIT; z++) {
            const float4* po = (const float4*)(g_po + ((size_t)z * QH + qidx) * HD + half * 8);
#pragma unroll
            for (int k4 = 0; k4 < 2; k4++) {
                float4 a = po[k4];
                acc[k4 * 4 + 0] = fmaf(a.x, c[z], acc[k4 * 4 + 0]);
                acc[k4 * 4 + 1] = fmaf(a.y, c[z], acc[k4 * 4 + 1]);
                acc[k4 * 4 + 2] = fmaf(a.z, c[z], acc[k4 * 4 + 2]);
                acc[k4 * 4 + 3] = fmaf(a.w, c[z], acc[k4 * 4 + 3]);
            }
        }
#pragma unroll
        for (int j = 0; j < 8; j++)
            xd[r][slot * 16 + half * 8 + j] = pk2(acc[j], acc[j]);
    }
    __syncthreads();

    const int jh = tid & 63;
    const int rg = tid >> 6;            // 0..3; rows rg, rg+4, rg+8, rg+12

    float2 b2 = *(const float2*)&lin_b[jh * 2];
    const u64 bias = pk2(b2.x, b2.y);
    u64 acc[4];
#pragma unroll
    for (int r = 0; r < 4; r++) acc[r] = bias;

    const u64* Wp = (const u64*)g_lwT;
#pragma unroll
    for (int d0 = 0; d0 < 128; d0 += 8) {
        u64 w[8];
#pragma unroll
        for (int i = 0; i < 8; i++) w[i] = Wp[(d0 + i) * 64 + jh];
#pragma unroll
        for (int i = 0; i < 8; i++) {
#pragma unroll
            for (int r = 0; r < 4; r++)
                acc[r] = fma2_(xd[rg + r * 4][d0 + i], w[i], acc[r]);
        }
    }
    u64* yp = (u64*)y;
#pragma unroll
    for (int r = 0; r < 4; r++)
        yp[(size_t)(row0 + rg + r * 4) * 64 + jh] = acc[r];
}

// ---------------------------------------------------------------------------
extern "C" void kernel_launch(void* const* d_in, const int* in_sizes, int n_in,
                              void* d_out, int out_size)
{
    const float* x    = (const float*)d_in[0];
    const int*   mraw = (const int*)  d_in[1];
    const float* wq   = (const float*)d_in[2];
    const float* wk   = (const float*)d_in[3];
    const float* wv   = (const float*)d_in[4];
    const float* lw   = (const float*)d_in[5];
    const float* lb   = (const float*)d_in[6];
    float*       y    = (float*)d_out;

    prep_kernel<<<256, 256>>>(x, wq, wk, wv, lw, mraw);
    qkv_kernel<<<dim3(ROWS / 32, 3), 256>>>();
    attn_kernel<<<dim3(SEQ / QTILE, NPAIR, KSPLIT), 256>>>();
    proj_kernel<<<ROWS / 16, 256>>>(lb, y);
}